// round 4
// baseline (speedup 1.0000x reference)
#include <cuda_runtime.h>
#include <math.h>

#define NMAX 100000
#define EMAX 1600000
#define KDIM 128   // inner dim for both GEMMs (Fin = Hid = 128)
#define NCHUNK 4

// ---------------- scratch (static device globals; no allocation) ------------
__device__ __align__(16) float d_g1[(size_t)NMAX * 128]; // x@W1 (unscaled)
__device__ __align__(16) float d_h1[(size_t)NMAX * 128]; // layer-1 output (post relu)
__device__ __align__(16) float d_g2[(size_t)NMAX * 64];  // h1@W2 (unscaled)
__device__ float d_dinv[NMAX];
__device__ int   d_counts[NMAX];
__device__ int   d_offsets[NMAX];
__device__ int   d_cursor[NMAX];
__device__ int   d_csr[EMAX];

// ---------------- CSR build -------------------------------------------------
__global__ void k_count(const int* __restrict__ ei, int E) {
    int e = blockIdx.x * blockDim.x + threadIdx.x;
    if (e < E) {
        int dst = ei[(size_t)E + e];
        atomicAdd(&d_counts[dst], 1);
    }
}

// single-block scan, warp-shuffle based (3 barriers per 1024-chunk)
__global__ void k_scan(int n) {
    __shared__ int wsum[32];
    int tid  = threadIdx.x;
    int lane = tid & 31;
    int wid  = tid >> 5;
    int run  = 0;
    for (int base = 0; base < n; base += 1024) {
        int i = base + tid;
        int v = (i < n) ? d_counts[i] : 0;
        int x = v;
        #pragma unroll
        for (int d = 1; d < 32; d <<= 1) {
            int t = __shfl_up_sync(0xffffffffu, x, d);
            if (lane >= d) x += t;
        }
        if (lane == 31) wsum[wid] = x;
        __syncthreads();
        if (wid == 0) {
            int s = wsum[lane];
            #pragma unroll
            for (int d = 1; d < 32; d <<= 1) {
                int t = __shfl_up_sync(0xffffffffu, s, d);
                if (lane >= d) s += t;
            }
            wsum[lane] = s;
        }
        __syncthreads();
        int warp_prefix = (wid > 0) ? wsum[wid - 1] : 0;
        int total       = wsum[31];
        int incl        = run + warp_prefix + x;
        if (i < n) {
            int off = incl - v;
            d_offsets[i] = off;
            d_cursor[i]  = off;
            d_dinv[i]    = rsqrtf((float)(1 + v));
        }
        run += total;
        __syncthreads();
    }
}

__global__ void k_fill(const int* __restrict__ ei, int E) {
    int e = blockIdx.x * blockDim.x + threadIdx.x;
    if (e < E) {
        int src = ei[e];
        int dst = ei[(size_t)E + e];
        int p = atomicAdd(&d_cursor[dst], 1);
        d_csr[p] = src;
    }
}

// ---------------- GEMM: G[r0+..] = A @ W[128,BN]  (row range) ---------------
template <int BN, int TN>
__global__ void __launch_bounds__(256)
k_gemm(const float* __restrict__ A, const float* __restrict__ W,
       float* __restrict__ G, int rbase, int M) {
    constexpr int BM = 128, BK = 16, TM = 8, NT = 256, K = KDIM;
    static_assert(BN / TN == 16, "layout");
    __shared__ __align__(16) float As[BK][BM];
    __shared__ __align__(16) float Bs[BK][BN];

    const int tid  = threadIdx.x;
    const int r0   = rbase + blockIdx.x * BM;
    const int tcol = tid & 15;
    const int trow = tid >> 4;

    float acc[TM][TN] = {};
    constexpr int A_F4 = (BM * BK) / (NT * 4);
    constexpr int B_F4 = (BK * BN) / (NT * 4);

    for (int kt = 0; kt < K; kt += BK) {
        #pragma unroll
        for (int i = 0; i < A_F4; i++) {
            int idx = tid + i * NT;
            int ar  = idx >> 2;
            int ac  = idx & 3;
            float4 v = make_float4(0.f, 0.f, 0.f, 0.f);
            int row = r0 + ar;
            if (row < M)
                v = *reinterpret_cast<const float4*>(A + (size_t)row * K + kt + ac * 4);
            As[ac * 4 + 0][ar] = v.x;
            As[ac * 4 + 1][ar] = v.y;
            As[ac * 4 + 2][ar] = v.z;
            As[ac * 4 + 3][ar] = v.w;
        }
        #pragma unroll
        for (int i = 0; i < B_F4; i++) {
            int idx = tid + i * NT;
            int br  = idx / (BN / 4);
            int bc  = idx % (BN / 4);
            *reinterpret_cast<float4*>(&Bs[br][bc * 4]) =
                *reinterpret_cast<const float4*>(W + (size_t)(kt + br) * BN + bc * 4);
        }
        __syncthreads();

        #pragma unroll
        for (int k = 0; k < BK; k++) {
            float rm[TM], rn[TN];
            float4 a0 = *reinterpret_cast<const float4*>(&As[k][trow * TM]);
            float4 a1 = *reinterpret_cast<const float4*>(&As[k][trow * TM + 4]);
            rm[0]=a0.x; rm[1]=a0.y; rm[2]=a0.z; rm[3]=a0.w;
            rm[4]=a1.x; rm[5]=a1.y; rm[6]=a1.z; rm[7]=a1.w;
            float4 b0 = *reinterpret_cast<const float4*>(&Bs[k][tcol * TN]);
            rn[0]=b0.x; rn[1]=b0.y; rn[2]=b0.z; rn[3]=b0.w;
            if constexpr (TN == 8) {
                float4 b1 = *reinterpret_cast<const float4*>(&Bs[k][tcol * TN + 4]);
                rn[4]=b1.x; rn[5]=b1.y; rn[6]=b1.z; rn[7]=b1.w;
            }
            #pragma unroll
            for (int i = 0; i < TM; i++)
                #pragma unroll
                for (int j = 0; j < TN; j++)
                    acc[i][j] += rm[i] * rn[j];
        }
        __syncthreads();
    }

    #pragma unroll
    for (int i = 0; i < TM; i++) {
        int row = r0 + trow * TM + i;
        if (row < M) {
            float* o = G + (size_t)row * BN + tcol * TN;
            #pragma unroll
            for (int j = 0; j < TN; j += 4)
                *reinterpret_cast<float4*>(o + j) =
                    make_float4(acc[i][j], acc[i][j+1], acc[i][j+2], acc[i][j+3]);
        }
    }
}

// ------ aggregation: out[i] = relu(dinv[i]*(Σ dinv[s]g[s] + dinv[i]g[i]) + b)
template <int F>
__global__ void k_agg(const float* __restrict__ g, const float* __restrict__ bias,
                      float* __restrict__ out, int nbase, int nend) {
    constexpr int V = F / 32;
    int w = nbase + ((blockIdx.x * blockDim.x + threadIdx.x) >> 5);
    if (w >= nend) return;
    int lane = threadIdx.x & 31;

    float dv = d_dinv[w];
    float acc[V];
    const float* self = g + (size_t)w * F + lane * V;
    if constexpr (V == 4) {
        float4 t = *reinterpret_cast<const float4*>(self);
        acc[0] = t.x * dv; acc[1] = t.y * dv; acc[2] = t.z * dv; acc[3] = t.w * dv;
    } else {
        float2 t = *reinterpret_cast<const float2*>(self);
        acc[0] = t.x * dv; acc[1] = t.y * dv;
    }

    int start = d_offsets[w];
    int cnt   = d_counts[w];
    for (int j = 0; j < cnt; j += 8) {
        int idx[8];
        float wgt[8];
        #pragma unroll
        for (int u = 0; u < 8; u++) {
            int jj = j + u;
            idx[u] = (jj < cnt) ? d_csr[start + jj] : w;
        }
        #pragma unroll
        for (int u = 0; u < 8; u++)
            wgt[u] = d_dinv[idx[u]];
        if constexpr (V == 4) {
            float4 t[8];
            #pragma unroll
            for (int u = 0; u < 8; u++)
                t[u] = *reinterpret_cast<const float4*>(g + (size_t)idx[u] * F + lane * 4);
            #pragma unroll
            for (int u = 0; u < 8; u++)
                if (j + u < cnt) {
                    acc[0] += t[u].x * wgt[u]; acc[1] += t[u].y * wgt[u];
                    acc[2] += t[u].z * wgt[u]; acc[3] += t[u].w * wgt[u];
                }
        } else {
            float2 t[8];
            #pragma unroll
            for (int u = 0; u < 8; u++)
                t[u] = *reinterpret_cast<const float2*>(g + (size_t)idx[u] * F + lane * 2);
            #pragma unroll
            for (int u = 0; u < 8; u++)
                if (j + u < cnt) {
                    acc[0] += t[u].x * wgt[u]; acc[1] += t[u].y * wgt[u];
                }
        }
    }

    float r[V];
    #pragma unroll
    for (int v = 0; v < V; v++) {
        float val = acc[v] * dv + __ldg(&bias[lane * V + v]);
        r[v] = val > 0.f ? val : 0.f;
    }
    float* o = out + (size_t)w * F + lane * V;
    if constexpr (V == 4) {
        *reinterpret_cast<float4*>(o) = make_float4(r[0], r[1], r[2], r[3]);
    } else {
        *reinterpret_cast<float2*>(o) = make_float2(r[0], r[1]);
    }
}

// ---------------- launch -----------------------------------------------------
extern "C" void kernel_launch(void* const* d_in, const int* in_sizes, int n_in,
                              void* d_out, int out_size) {
    const float* x  = (const float*)d_in[0];
    const int*   ei = (const int*)d_in[1];   // JAX downcasts int64 -> int32
    const float* W1 = (const float*)d_in[2];
    const float* b1 = (const float*)d_in[3];
    const float* W2 = (const float*)d_in[4];
    const float* b2 = (const float*)d_in[5];
    float* out = (float*)d_out;

    const int M = in_sizes[0] / 128;  // 100000 nodes
    const int E = in_sizes[1] / 2;    // 1600000 edges

    float *g1, *h1, *g2;
    int* counts;
    cudaGetSymbolAddress((void**)&g1, d_g1);
    cudaGetSymbolAddress((void**)&h1, d_h1);
    cudaGetSymbolAddress((void**)&g2, d_g2);
    cudaGetSymbolAddress((void**)&counts, d_counts);

    // one-time resource setup (not work; captured graph is identical per call)
    static cudaStream_t s1 = nullptr;
    static cudaEvent_t eFork = nullptr, eCsr = nullptr, eG1 = nullptr,
                       eA[NCHUNK] = {}, eB = nullptr;
    if (!s1) {
        cudaStreamCreateWithFlags(&s1, cudaStreamNonBlocking);
        cudaEventCreateWithFlags(&eFork, cudaEventDisableTiming);
        cudaEventCreateWithFlags(&eCsr,  cudaEventDisableTiming);
        cudaEventCreateWithFlags(&eG1,   cudaEventDisableTiming);
        for (int i = 0; i < NCHUNK; i++)
            cudaEventCreateWithFlags(&eA[i], cudaEventDisableTiming);
        cudaEventCreateWithFlags(&eB, cudaEventDisableTiming);
    }

    // fork side stream from default stream
    cudaEventRecord(eFork, 0);
    cudaStreamWaitEvent(s1, eFork, 0);

    // --- s1: CSR build (independent of GEMM1) ---
    cudaMemsetAsync(counts, 0, (size_t)M * sizeof(int), s1);
    k_count<<<(E + 255) / 256, 256, 0, s1>>>(ei, E);
    k_scan <<<1, 1024, 0, s1>>>(M);
    k_fill <<<(E + 255) / 256, 256, 0, s1>>>(ei, E);
    cudaEventRecord(eCsr, s1);

    // --- s0: GEMM1 (full) ---
    k_gemm<128, 8><<<(M + 127) / 128, 256>>>(x, W1, g1, 0, M);
    cudaEventRecord(eG1, 0);

    // agg1 needs CSR + g1
    cudaStreamWaitEvent(0, eCsr, 0);
    cudaStreamWaitEvent(s1, eG1, 0);   // s1 will run gemm2 chunks reading h1

    // --- pipelined: agg1 chunk i on s0, gemm2 chunk i on s1 ---
    const int chunk = (M + NCHUNK - 1) / NCHUNK;
    for (int c = 0; c < NCHUNK; c++) {
        int lo = c * chunk;
        int hi = min(M, lo + chunk);
        int nn = hi - lo;
        k_agg<128><<<((nn * 32) + 255) / 256, 256>>>(g1, b1, h1, lo, hi);
        cudaEventRecord(eA[c], 0);
        cudaStreamWaitEvent(s1, eA[c], 0);
        k_gemm<64, 4><<<(nn + 127) / 128, 256, 0, s1>>>(h1, W2, g2, lo, hi);
    }
    cudaEventRecord(eB, s1);
    cudaStreamWaitEvent(0, eB, 0);     // join: all g2 ready

    // --- s0: final aggregation ---
    k_agg<64><<<((M * 32) + 255) / 256, 256>>>(g2, b2, out, 0, M);
}

// round 5
// speedup vs baseline: 1.0330x; 1.0330x over previous
#include <cuda_runtime.h>
#include <math.h>

#define NMAX 100000
#define EMAX 1600000
#define KDIM 128   // inner dim for both GEMMs (Fin = Hid = 128)

// ---------------- scratch (static device globals; no allocation) ------------
__device__ __align__(16) float d_g1[(size_t)NMAX * 128]; // x@W1 (unscaled)
__device__ __align__(16) float d_h1[(size_t)NMAX * 128]; // layer-1 output (post relu)
__device__ __align__(16) float d_g2[(size_t)NMAX * 64];  // h1@W2 (unscaled)
__device__ float d_dinv[NMAX];
__device__ int   d_counts[NMAX];
__device__ int   d_offsets[NMAX];
__device__ int   d_cursor[NMAX];
__device__ int   d_csr[EMAX];

// ---------------- CSR build -------------------------------------------------
__global__ void k_count(const int* __restrict__ ei, int E) {
    int e = blockIdx.x * blockDim.x + threadIdx.x;
    if (e < E) {
        int dst = ei[(size_t)E + e];
        atomicAdd(&d_counts[dst], 1);
    }
}

// single-block scan, warp-shuffle based (3 barriers per 1024-chunk)
__global__ void k_scan(int n) {
    __shared__ int wsum[32];
    int tid  = threadIdx.x;
    int lane = tid & 31;
    int wid  = tid >> 5;
    int run  = 0;
    for (int base = 0; base < n; base += 1024) {
        int i = base + tid;
        int v = (i < n) ? d_counts[i] : 0;
        int x = v;
        #pragma unroll
        for (int d = 1; d < 32; d <<= 1) {
            int t = __shfl_up_sync(0xffffffffu, x, d);
            if (lane >= d) x += t;
        }
        if (lane == 31) wsum[wid] = x;
        __syncthreads();
        if (wid == 0) {
            int s = wsum[lane];
            #pragma unroll
            for (int d = 1; d < 32; d <<= 1) {
                int t = __shfl_up_sync(0xffffffffu, s, d);
                if (lane >= d) s += t;
            }
            wsum[lane] = s;
        }
        __syncthreads();
        int warp_prefix = (wid > 0) ? wsum[wid - 1] : 0;
        int total       = wsum[31];
        int incl        = run + warp_prefix + x;
        if (i < n) {
            int off = incl - v;
            d_offsets[i] = off;
            d_cursor[i]  = off;
            d_dinv[i]    = rsqrtf((float)(1 + v));
        }
        run += total;
        __syncthreads();
    }
}

__global__ void k_fill(const int* __restrict__ ei, int E) {
    int e = blockIdx.x * blockDim.x + threadIdx.x;
    if (e < E) {
        int src = ei[e];
        int dst = ei[(size_t)E + e];
        int p = atomicAdd(&d_cursor[dst], 1);
        d_csr[p] = src;
    }
}

// ------- double-buffered GEMM: G = A[M,128] @ W[128,BN] ---------------------
// BM=128, BK=16, TM=8, NT=256; BN/TN == 16.
template <int BN, int TN>
__global__ void __launch_bounds__(256)
k_gemm(const float* __restrict__ A, const float* __restrict__ W,
       float* __restrict__ G, int M) {
    constexpr int BM = 128, BK = 16, TM = 8, NT = 256, K = KDIM;
    constexpr int NKT = K / BK;                 // 8
    static_assert(BN / TN == 16, "layout");
    constexpr int A_F4 = (BM * BK) / (NT * 4);  // 2
    constexpr int B_F4 = (BK * BN) / (NT * 4);  // 2 (BN=128) or 1 (BN=64)

    __shared__ __align__(16) float As[2][BK][BM];
    __shared__ __align__(16) float Bs[2][BK][BN];

    const int tid  = threadIdx.x;
    const int r0   = blockIdx.x * BM;
    const int tcol = tid & 15;
    const int trow = tid >> 4;

    // per-thread load coordinates (A)
    int a_ar[A_F4], a_ac[A_F4];
    #pragma unroll
    for (int i = 0; i < A_F4; i++) {
        int idx = tid + i * NT;
        a_ar[i] = idx >> 2;     // row within tile (BK/4 = 4 float4 per row)
        a_ac[i] = idx & 3;      // float4 column
    }
    int b_br[B_F4], b_bc[B_F4];
    #pragma unroll
    for (int i = 0; i < B_F4; i++) {
        int idx = tid + i * NT;
        b_br[i] = idx / (BN / 4);
        b_bc[i] = idx % (BN / 4);
    }

    float acc[TM][TN] = {};
    float4 pa[A_F4], pb[B_F4];

    // prologue: load tile 0
    #pragma unroll
    for (int i = 0; i < A_F4; i++) {
        int row = r0 + a_ar[i];
        pa[i] = (row < M)
              ? *reinterpret_cast<const float4*>(A + (size_t)row * K + a_ac[i] * 4)
              : make_float4(0.f, 0.f, 0.f, 0.f);
    }
    #pragma unroll
    for (int i = 0; i < B_F4; i++)
        pb[i] = *reinterpret_cast<const float4*>(W + (size_t)b_br[i] * BN + b_bc[i] * 4);
    #pragma unroll
    for (int i = 0; i < A_F4; i++) {
        As[0][a_ac[i] * 4 + 0][a_ar[i]] = pa[i].x;
        As[0][a_ac[i] * 4 + 1][a_ar[i]] = pa[i].y;
        As[0][a_ac[i] * 4 + 2][a_ar[i]] = pa[i].z;
        As[0][a_ac[i] * 4 + 3][a_ar[i]] = pa[i].w;
    }
    #pragma unroll
    for (int i = 0; i < B_F4; i++)
        *reinterpret_cast<float4*>(&Bs[0][b_br[i]][b_bc[i] * 4]) = pb[i];
    __syncthreads();

    int buf = 0;
    #pragma unroll
    for (int kt = 0; kt < NKT; kt++) {
        // prefetch tile kt+1 into registers
        if (kt + 1 < NKT) {
            int koff = (kt + 1) * BK;
            #pragma unroll
            for (int i = 0; i < A_F4; i++) {
                int row = r0 + a_ar[i];
                pa[i] = (row < M)
                      ? *reinterpret_cast<const float4*>(A + (size_t)row * K + koff + a_ac[i] * 4)
                      : make_float4(0.f, 0.f, 0.f, 0.f);
            }
            #pragma unroll
            for (int i = 0; i < B_F4; i++)
                pb[i] = *reinterpret_cast<const float4*>(W + (size_t)(koff + b_br[i]) * BN + b_bc[i] * 4);
        }

        // compute on smem[buf]
        #pragma unroll
        for (int k = 0; k < BK; k++) {
            float rm[TM], rn[TN];
            float4 a0 = *reinterpret_cast<const float4*>(&As[buf][k][trow * TM]);
            float4 a1 = *reinterpret_cast<const float4*>(&As[buf][k][trow * TM + 4]);
            rm[0]=a0.x; rm[1]=a0.y; rm[2]=a0.z; rm[3]=a0.w;
            rm[4]=a1.x; rm[5]=a1.y; rm[6]=a1.z; rm[7]=a1.w;
            float4 b0 = *reinterpret_cast<const float4*>(&Bs[buf][k][tcol * TN]);
            rn[0]=b0.x; rn[1]=b0.y; rn[2]=b0.z; rn[3]=b0.w;
            if constexpr (TN == 8) {
                float4 b1 = *reinterpret_cast<const float4*>(&Bs[buf][k][tcol * TN + 4]);
                rn[4]=b1.x; rn[5]=b1.y; rn[6]=b1.z; rn[7]=b1.w;
            }
            #pragma unroll
            for (int i = 0; i < TM; i++)
                #pragma unroll
                for (int j = 0; j < TN; j++)
                    acc[i][j] += rm[i] * rn[j];
        }

        // stage tile kt+1 into the other buffer
        if (kt + 1 < NKT) {
            #pragma unroll
            for (int i = 0; i < A_F4; i++) {
                As[buf ^ 1][a_ac[i] * 4 + 0][a_ar[i]] = pa[i].x;
                As[buf ^ 1][a_ac[i] * 4 + 1][a_ar[i]] = pa[i].y;
                As[buf ^ 1][a_ac[i] * 4 + 2][a_ar[i]] = pa[i].z;
                As[buf ^ 1][a_ac[i] * 4 + 3][a_ar[i]] = pa[i].w;
            }
            #pragma unroll
            for (int i = 0; i < B_F4; i++)
                *reinterpret_cast<float4*>(&Bs[buf ^ 1][b_br[i]][b_bc[i] * 4]) = pb[i];
            __syncthreads();
        }
        buf ^= 1;
    }

    #pragma unroll
    for (int i = 0; i < TM; i++) {
        int row = r0 + trow * TM + i;
        if (row < M) {
            float* o = G + (size_t)row * BN + tcol * TN;
            #pragma unroll
            for (int j = 0; j < TN; j += 4)
                *reinterpret_cast<float4*>(o + j) =
                    make_float4(acc[i][j], acc[i][j+1], acc[i][j+2], acc[i][j+3]);
        }
    }
}

// ------ aggregation: out[i] = relu(dinv[i]*(Σ dinv[s]g[s] + dinv[i]g[i]) + b)
template <int F>
__global__ void k_agg(const float* __restrict__ g, const float* __restrict__ bias,
                      float* __restrict__ out, int n) {
    constexpr int V = F / 32;
    int w = (blockIdx.x * blockDim.x + threadIdx.x) >> 5;
    if (w >= n) return;
    int lane = threadIdx.x & 31;

    float dv = d_dinv[w];
    float acc[V];
    const float* self = g + (size_t)w * F + lane * V;
    if constexpr (V == 4) {
        float4 t = *reinterpret_cast<const float4*>(self);
        acc[0] = t.x * dv; acc[1] = t.y * dv; acc[2] = t.z * dv; acc[3] = t.w * dv;
    } else {
        float2 t = *reinterpret_cast<const float2*>(self);
        acc[0] = t.x * dv; acc[1] = t.y * dv;
    }

    int start = d_offsets[w];
    int cnt   = d_counts[w];
    for (int j = 0; j < cnt; j += 8) {
        int idx[8];
        float wgt[8];
        #pragma unroll
        for (int u = 0; u < 8; u++) {
            int jj = j + u;
            idx[u] = (jj < cnt) ? d_csr[start + jj] : w;
        }
        #pragma unroll
        for (int u = 0; u < 8; u++)
            wgt[u] = d_dinv[idx[u]];
        if constexpr (V == 4) {
            float4 t[8];
            #pragma unroll
            for (int u = 0; u < 8; u++)
                t[u] = *reinterpret_cast<const float4*>(g + (size_t)idx[u] * F + lane * 4);
            #pragma unroll
            for (int u = 0; u < 8; u++)
                if (j + u < cnt) {
                    acc[0] += t[u].x * wgt[u]; acc[1] += t[u].y * wgt[u];
                    acc[2] += t[u].z * wgt[u]; acc[3] += t[u].w * wgt[u];
                }
        } else {
            float2 t[8];
            #pragma unroll
            for (int u = 0; u < 8; u++)
                t[u] = *reinterpret_cast<const float2*>(g + (size_t)idx[u] * F + lane * 2);
            #pragma unroll
            for (int u = 0; u < 8; u++)
                if (j + u < cnt) {
                    acc[0] += t[u].x * wgt[u]; acc[1] += t[u].y * wgt[u];
                }
        }
    }

    float r[V];
    #pragma unroll
    for (int v = 0; v < V; v++) {
        float val = acc[v] * dv + __ldg(&bias[lane * V + v]);
        r[v] = val > 0.f ? val : 0.f;
    }
    float* o = out + (size_t)w * F + lane * V;
    if constexpr (V == 4) {
        *reinterpret_cast<float4*>(o) = make_float4(r[0], r[1], r[2], r[3]);
    } else {
        *reinterpret_cast<float2*>(o) = make_float2(r[0], r[1]);
    }
}

// ---------------- launch -----------------------------------------------------
extern "C" void kernel_launch(void* const* d_in, const int* in_sizes, int n_in,
                              void* d_out, int out_size) {
    const float* x  = (const float*)d_in[0];
    const int*   ei = (const int*)d_in[1];   // JAX downcasts int64 -> int32
    const float* W1 = (const float*)d_in[2];
    const float* b1 = (const float*)d_in[3];
    const float* W2 = (const float*)d_in[4];
    const float* b2 = (const float*)d_in[5];
    float* out = (float*)d_out;

    const int M = in_sizes[0] / 128;  // 100000 nodes
    const int E = in_sizes[1] / 2;    // 1600000 edges

    float *g1, *h1, *g2;
    int* counts;
    cudaGetSymbolAddress((void**)&g1, d_g1);
    cudaGetSymbolAddress((void**)&h1, d_h1);
    cudaGetSymbolAddress((void**)&g2, d_g2);
    cudaGetSymbolAddress((void**)&counts, d_counts);

    // one-time resource setup (identical captured graph every call)
    static cudaStream_t s1 = nullptr;
    static cudaEvent_t eFork = nullptr, eCsr = nullptr;
    if (!s1) {
        cudaStreamCreateWithFlags(&s1, cudaStreamNonBlocking);
        cudaEventCreateWithFlags(&eFork, cudaEventDisableTiming);
        cudaEventCreateWithFlags(&eCsr,  cudaEventDisableTiming);
    }

    // fork: CSR build on s1 runs concurrently with compute-bound GEMM1 on s0
    cudaEventRecord(eFork, 0);
    cudaStreamWaitEvent(s1, eFork, 0);

    cudaMemsetAsync(counts, 0, (size_t)M * sizeof(int), s1);
    k_count<<<(E + 255) / 256, 256, 0, s1>>>(ei, E);
    k_scan <<<1, 1024, 0, s1>>>(M);
    k_fill <<<(E + 255) / 256, 256, 0, s1>>>(ei, E);
    cudaEventRecord(eCsr, s1);

    k_gemm<128, 8><<<(M + 127) / 128, 256>>>(x, W1, g1, M);

    cudaStreamWaitEvent(0, eCsr, 0);   // join before agg1

    k_agg<128><<<((M * 32) + 255) / 256, 256>>>(g1, b1, h1, M);
    k_gemm<64, 4><<<(M + 127) / 128, 256>>>(h1, W2, g2, M);
    k_agg<64><<<((M * 32) + 255) / 256, 256>>>(g2, b2, out, M);
}

// round 6
// speedup vs baseline: 1.2143x; 1.1755x over previous
#include <cuda_runtime.h>
#include <math.h>

#define NMAX 100000
#define EMAX 1600000
#define KDIM 128

// ---------------- scratch (static device globals; no allocation) ------------
__device__ __align__(16) float d_g1[(size_t)NMAX * 128]; // x@W1 (unscaled)
__device__ __align__(16) float d_h1[(size_t)NMAX * 128]; // layer-1 output
__device__ __align__(16) float d_g2[(size_t)NMAX * 64];  // h1@W2 (unscaled)
__device__ float d_dinv[NMAX];
__device__ int   d_counts[NMAX];
__device__ int   d_offsets[NMAX];
__device__ int   d_cursor[NMAX];
__device__ int   d_csr[EMAX];

// ---------------- CSR build -------------------------------------------------
__global__ void k_count(const int* __restrict__ ei, int E) {
    int e = blockIdx.x * blockDim.x + threadIdx.x;
    if (e < E) atomicAdd(&d_counts[ei[(size_t)E + e]], 1);
}

__global__ void k_scan(int n) {
    __shared__ int wsum[32];
    int tid  = threadIdx.x;
    int lane = tid & 31;
    int wid  = tid >> 5;
    int run  = 0;
    for (int base = 0; base < n; base += 1024) {
        int i = base + tid;
        int v = (i < n) ? d_counts[i] : 0;
        int x = v;
        #pragma unroll
        for (int d = 1; d < 32; d <<= 1) {
            int t = __shfl_up_sync(0xffffffffu, x, d);
            if (lane >= d) x += t;
        }
        if (lane == 31) wsum[wid] = x;
        __syncthreads();
        if (wid == 0) {
            int s = wsum[lane];
            #pragma unroll
            for (int d = 1; d < 32; d <<= 1) {
                int t = __shfl_up_sync(0xffffffffu, s, d);
                if (lane >= d) s += t;
            }
            wsum[lane] = s;
        }
        __syncthreads();
        int warp_prefix = (wid > 0) ? wsum[wid - 1] : 0;
        int total       = wsum[31];
        int incl        = run + warp_prefix + x;
        if (i < n) {
            int off = incl - v;
            d_offsets[i] = off;
            d_cursor[i]  = off;
            d_dinv[i]    = rsqrtf((float)(1 + v));
        }
        run += total;
        __syncthreads();
    }
}

__global__ void k_fill(const int* __restrict__ ei, int E) {
    int e = blockIdx.x * blockDim.x + threadIdx.x;
    if (e < E) {
        int src = ei[e];
        int dst = ei[(size_t)E + e];
        int p = atomicAdd(&d_cursor[dst], 1);
        d_csr[p] = src;
    }
}

// ---------------- tf32 tensor-core GEMM: G = A[M,128] @ W[128,BN] -----------
__device__ __forceinline__ float to_tf32(float x) {
    float r;
    asm("cvt.rna.tf32.f32 %0, %1;" : "=f"(r) : "f"(x));
    return r;
}

template <int BN>
__global__ void __launch_bounds__(256)
k_gemm_tc(const float* __restrict__ A, const float* __restrict__ W,
          float* __restrict__ G, int M) {
    constexpr int K  = KDIM, BM = 128;
    constexpr int SA = 132;          // padded A stride (floats): conflict-free frags
    constexpr int SB = BN + 8;       // padded W stride
    constexpr int NT = BN / 8;       // n-tiles per warp

    extern __shared__ float sm[];
    float* As = sm;                  // [BM][SA]
    float* Ws = sm + BM * SA;        // [K][SB]

    const int tid = threadIdx.x;
    const int r0  = blockIdx.x * BM;

    // load A tile (full K), tf32-round, zero-pad OOB rows
    #pragma unroll
    for (int it = 0; it < (BM * (K / 4)) / 256; it++) {
        int i   = tid + it * 256;
        int row = i >> 5;            // K/4 = 32 float4 per row
        int c4  = i & 31;
        float4 v = make_float4(0.f, 0.f, 0.f, 0.f);
        if (r0 + row < M)
            v = *reinterpret_cast<const float4*>(A + (size_t)(r0 + row) * K + c4 * 4);
        float* p = As + row * SA + c4 * 4;
        p[0] = to_tf32(v.x); p[1] = to_tf32(v.y);
        p[2] = to_tf32(v.z); p[3] = to_tf32(v.w);
    }
    // load W (full K x BN), tf32-round
    #pragma unroll
    for (int it = 0; it < (K * (BN / 4)) / 256; it++) {
        int i   = tid + it * 256;
        int row = i / (BN / 4);
        int c4  = i % (BN / 4);
        float4 v = *reinterpret_cast<const float4*>(W + (size_t)row * BN + c4 * 4);
        float* p = Ws + row * SB + c4 * 4;
        p[0] = to_tf32(v.x); p[1] = to_tf32(v.y);
        p[2] = to_tf32(v.z); p[3] = to_tf32(v.w);
    }
    __syncthreads();

    const int warp = tid >> 5;
    const int lane = tid & 31;
    const int g    = lane >> 2;      // 0..7
    const int tg   = lane & 3;       // 0..3
    const int wr   = warp * 16;      // warp's row base within tile

    float acc[NT][4];
    #pragma unroll
    for (int nt = 0; nt < NT; nt++) {
        acc[nt][0] = 0.f; acc[nt][1] = 0.f; acc[nt][2] = 0.f; acc[nt][3] = 0.f;
    }

    #pragma unroll
    for (int kc = 0; kc < K / 8; kc++) {
        int c = kc * 8 + tg;
        float a0 = As[(wr + g)     * SA + c];
        float a1 = As[(wr + g + 8) * SA + c];
        float a2 = As[(wr + g)     * SA + c + 4];
        float a3 = As[(wr + g + 8) * SA + c + 4];
        #pragma unroll
        for (int nt = 0; nt < NT; nt++) {
            float b0 = Ws[c       * SB + nt * 8 + g];
            float b1 = Ws[(c + 4) * SB + nt * 8 + g];
            asm volatile(
                "mma.sync.aligned.m16n8k8.row.col.f32.tf32.tf32.f32 "
                "{%0,%1,%2,%3}, {%4,%5,%6,%7}, {%8,%9}, {%0,%1,%2,%3};"
                : "+f"(acc[nt][0]), "+f"(acc[nt][1]),
                  "+f"(acc[nt][2]), "+f"(acc[nt][3])
                : "r"(__float_as_uint(a0)), "r"(__float_as_uint(a1)),
                  "r"(__float_as_uint(a2)), "r"(__float_as_uint(a3)),
                  "r"(__float_as_uint(b0)), "r"(__float_as_uint(b1)));
        }
    }

    // epilogue: c0,c1 -> (row, 2tg..2tg+1), c2,c3 -> (row+8, ...)
    int rowA = r0 + wr + g;
    int rowB = rowA + 8;
    #pragma unroll
    for (int nt = 0; nt < NT; nt++) {
        int col = nt * 8 + 2 * tg;
        if (rowA < M)
            *reinterpret_cast<float2*>(G + (size_t)rowA * BN + col) =
                make_float2(acc[nt][0], acc[nt][1]);
        if (rowB < M)
            *reinterpret_cast<float2*>(G + (size_t)rowB * BN + col) =
                make_float2(acc[nt][2], acc[nt][3]);
    }
}

// ------ aggregation: out[i] = relu(dinv[i]*(Σ dinv[s]g[s] + dinv[i]g[i]) + b)
template <int F>
__global__ void k_agg(const float* __restrict__ g, const float* __restrict__ bias,
                      float* __restrict__ out, int n) {
    constexpr int V = F / 32;
    int w = (blockIdx.x * blockDim.x + threadIdx.x) >> 5;
    if (w >= n) return;
    int lane = threadIdx.x & 31;

    float dv = d_dinv[w];
    float acc[V];
    const float* self = g + (size_t)w * F + lane * V;
    if constexpr (V == 4) {
        float4 t = *reinterpret_cast<const float4*>(self);
        acc[0] = t.x * dv; acc[1] = t.y * dv; acc[2] = t.z * dv; acc[3] = t.w * dv;
    } else {
        float2 t = *reinterpret_cast<const float2*>(self);
        acc[0] = t.x * dv; acc[1] = t.y * dv;
    }

    int start = d_offsets[w];
    int cnt   = d_counts[w];
    for (int j = 0; j < cnt; j += 8) {
        int idx[8];
        float wgt[8];
        #pragma unroll
        for (int u = 0; u < 8; u++) {
            int jj = j + u;
            idx[u] = (jj < cnt) ? d_csr[start + jj] : w;
        }
        #pragma unroll
        for (int u = 0; u < 8; u++)
            wgt[u] = d_dinv[idx[u]];
        if constexpr (V == 4) {
            float4 t[8];
            #pragma unroll
            for (int u = 0; u < 8; u++)
                t[u] = *reinterpret_cast<const float4*>(g + (size_t)idx[u] * F + lane * 4);
            #pragma unroll
            for (int u = 0; u < 8; u++)
                if (j + u < cnt) {
                    acc[0] += t[u].x * wgt[u]; acc[1] += t[u].y * wgt[u];
                    acc[2] += t[u].z * wgt[u]; acc[3] += t[u].w * wgt[u];
                }
        } else {
            float2 t[8];
            #pragma unroll
            for (int u = 0; u < 8; u++)
                t[u] = *reinterpret_cast<const float2*>(g + (size_t)idx[u] * F + lane * 2);
            #pragma unroll
            for (int u = 0; u < 8; u++)
                if (j + u < cnt) {
                    acc[0] += t[u].x * wgt[u]; acc[1] += t[u].y * wgt[u];
                }
        }
    }

    float r[V];
    #pragma unroll
    for (int v = 0; v < V; v++) {
        float val = acc[v] * dv + __ldg(&bias[lane * V + v]);
        r[v] = val > 0.f ? val : 0.f;
    }
    float* o = out + (size_t)w * F + lane * V;
    if constexpr (V == 4) {
        *reinterpret_cast<float4*>(o) = make_float4(r[0], r[1], r[2], r[3]);
    } else {
        *reinterpret_cast<float2*>(o) = make_float2(r[0], r[1]);
    }
}

// ---------------- launch -----------------------------------------------------
extern "C" void kernel_launch(void* const* d_in, const int* in_sizes, int n_in,
                              void* d_out, int out_size) {
    const float* x  = (const float*)d_in[0];
    const int*   ei = (const int*)d_in[1];
    const float* W1 = (const float*)d_in[2];
    const float* b1 = (const float*)d_in[3];
    const float* W2 = (const float*)d_in[4];
    const float* b2 = (const float*)d_in[5];
    float* out = (float*)d_out;

    const int M = in_sizes[0] / 128;  // 100000 nodes
    const int E = in_sizes[1] / 2;    // 1600000 edges

    constexpr int SMEM1 = (128 * 132 + 128 * (128 + 8)) * 4;  // 137216
    constexpr int SMEM2 = (128 * 132 + 128 * (64 + 8))  * 4;  // 104448

    float *g1, *h1, *g2;
    int* counts;
    cudaGetSymbolAddress((void**)&g1, d_g1);
    cudaGetSymbolAddress((void**)&h1, d_h1);
    cudaGetSymbolAddress((void**)&g2, d_g2);
    cudaGetSymbolAddress((void**)&counts, d_counts);

    // one-time resource setup (identical captured graph every call)
    static cudaStream_t s1 = nullptr;
    static cudaEvent_t eFork = nullptr, eCsr = nullptr;
    if (!s1) {
        cudaStreamCreateWithFlags(&s1, cudaStreamNonBlocking);
        cudaEventCreateWithFlags(&eFork, cudaEventDisableTiming);
        cudaEventCreateWithFlags(&eCsr,  cudaEventDisableTiming);
        cudaFuncSetAttribute(k_gemm_tc<128>,
                             cudaFuncAttributeMaxDynamicSharedMemorySize, SMEM1);
        cudaFuncSetAttribute(k_gemm_tc<64>,
                             cudaFuncAttributeMaxDynamicSharedMemorySize, SMEM2);
    }

    // fork: CSR build on s1 runs concurrently with GEMM1 on s0
    cudaEventRecord(eFork, 0);
    cudaStreamWaitEvent(s1, eFork, 0);

    cudaMemsetAsync(counts, 0, (size_t)M * sizeof(int), s1);
    k_count<<<(E + 255) / 256, 256, 0, s1>>>(ei, E);
    k_scan <<<1, 1024, 0, s1>>>(M);
    k_fill <<<(E + 255) / 256, 256, 0, s1>>>(ei, E);
    cudaEventRecord(eCsr, s1);

    k_gemm_tc<128><<<(M + 127) / 128, 256, SMEM1>>>(x, W1, g1, M);

    cudaStreamWaitEvent(0, eCsr, 0);   // join before agg1

    k_agg<128><<<((M * 32) + 255) / 256, 256>>>(g1, b1, h1, M);
    k_gemm_tc<64><<<(M + 127) / 128, 256, SMEM2>>>(h1, W2, g2, M);
    k_agg<64><<<((M * 32) + 255) / 256, 256>>>(g2, b2, out, M);
}